// round 4
// baseline (speedup 1.0000x reference)
#include <cuda_runtime.h>
#include <cuda_bf16.h>
#include <math.h>
#include <cstddef>

#define T_DIM 512
#define B_DIM 128
#define D_DIM 256
#define H_DIM 512

typedef unsigned long long u64;

// Scratch for precomputed input projection (+ biases). __device__ global =
// the sanctioned allocation-free scratch mechanism.
__device__ float g_xin[(size_t)T_DIM * B_DIM * H_DIM];

__device__ __forceinline__ void fma2(u64 &acc, u64 a, u64 b) {
    asm("fma.rn.f32x2 %0, %1, %2, %0;" : "+l"(acc) : "l"(a), "l"(b));
}
__device__ __forceinline__ float f2sum(u64 v) {
    float2 f = *reinterpret_cast<float2 *>(&v);
    return f.x + f.y;
}

// ---------------------------------------------------------------------------
// Kernel 1: xin[t,b,n] = x[t,b,:] . W_in[n,:] + b_in[n] + b_lat[n]
// GEMM: M = T*B = 65536, N = 512, K = 256. Unchanged from R2 (known good).
// ---------------------------------------------------------------------------
__global__ void __launch_bounds__(256, 1)
xin_gemm(const float *__restrict__ x, const float *__restrict__ W_in,
         const float *__restrict__ b_in, const float *__restrict__ b_lat) {
    __shared__ float As[128 * 16];   // [m][k]
    __shared__ float Bs[128 * 18];   // [n][k], padded

    const int tid = threadIdx.x;
    const int tx = tid & 15;
    const int ty = tid >> 4;
    const int m0 = blockIdx.y * 128;
    const int n0 = blockIdx.x * 128;

    u64 acc[8][8];
#pragma unroll
    for (int i = 0; i < 8; i++)
#pragma unroll
        for (int j = 0; j < 8; j++) acc[i][j] = 0ull;

    for (int kc = 0; kc < D_DIM; kc += 16) {
        __syncthreads();
#pragma unroll
        for (int u = 0; u < 2; u++) {
            int idx = tid + u * 256;
            int row = idx >> 2, c4 = idx & 3;
            float4 v = *reinterpret_cast<const float4 *>(
                &x[(size_t)(m0 + row) * D_DIM + kc + c4 * 4]);
            *reinterpret_cast<float4 *>(&As[row * 16 + c4 * 4]) = v;
        }
#pragma unroll
        for (int u = 0; u < 4; u++) {
            int idx = tid + u * 256;
            int row = idx >> 3, cp = idx & 7;
            float2 v = *reinterpret_cast<const float2 *>(
                &W_in[(size_t)(n0 + row) * D_DIM + kc + cp * 2]);
            *reinterpret_cast<float2 *>(&Bs[row * 18 + cp * 2]) = v;
        }
        __syncthreads();

        const u64 *As2 = reinterpret_cast<const u64 *>(As);
        const u64 *Bs2 = reinterpret_cast<const u64 *>(Bs);
#pragma unroll
        for (int kp = 0; kp < 8; kp++) {
            u64 a2[8], b2[8];
#pragma unroll
            for (int i = 0; i < 8; i++) a2[i] = As2[(ty * 8 + i) * 8 + kp];
#pragma unroll
            for (int j = 0; j < 8; j++) b2[j] = Bs2[(tx + 16 * j) * 9 + kp];
#pragma unroll
            for (int i = 0; i < 8; i++)
#pragma unroll
                for (int j = 0; j < 8; j++) fma2(acc[i][j], a2[i], b2[j]);
        }
    }

#pragma unroll
    for (int j = 0; j < 8; j++) {
        int n = n0 + tx + 16 * j;
        float bias = __ldg(&b_in[n]) + __ldg(&b_lat[n]);
#pragma unroll
        for (int i = 0; i < 8; i++) {
            g_xin[(size_t)(m0 + ty * 8 + i) * H_DIM + n] = f2sum(acc[i][j]) + bias;
        }
    }
}

// ---------------------------------------------------------------------------
// Kernel 2: the scan. 16 clusters x 8 CTAs, 512 threads/CTA (16 warps).
// Cluster c owns batches [c*8, c*8+8); CTA rank r owns output rows
// [r*64, r*64+64) with its W_lat slice resident in smem.
// Warp w -> 4 j rows; lane = (a = b-half, ks = 16-way K split);
// per-lane tile 4jj x 4bb; halving-tree shuffle reduction (15 SHFL/lane)
// leaves exactly one output per lane -> direct tanh + STG.
// ---------------------------------------------------------------------------
#define SMEM_SCAN_FLOATS (64 * 512 + 8 * 512)

__global__ void __cluster_dims__(8, 1, 1) __launch_bounds__(512, 1)
rnn_scan(const float *__restrict__ h0, const float *__restrict__ W_lat,
         float *__restrict__ out) {
    extern __shared__ float smem[];
    float *Wsm = smem;                    // 64 x 512
    float *hsm = smem + 64 * 512;         // 8 x 512

    const int tid = threadIdx.x;
    const int r = blockIdx.x & 7;   // cluster rank -> j-slice
    const int g = blockIdx.x >> 3;  // cluster id  -> batch group
    const int j0g = r * 64;
    const int b0 = g * 8;

    // Load W_lat rows [j0g, j0g+64) into smem (once). 8192 float4 / 512 thr.
    {
        const float4 *src = reinterpret_cast<const float4 *>(W_lat + (size_t)j0g * H_DIM);
        float4 *dst = reinterpret_cast<float4 *>(Wsm);
#pragma unroll
        for (int u = 0; u < 16; u++) dst[tid + 512 * u] = src[tid + 512 * u];
    }

    const int lane = tid & 31;
    const int w = tid >> 5;        // warp 0..15 -> j rows [w*4, w*4+4)
    const int a = lane >> 4;       // batch half: b = b0 + a*4 .. +4
    const int ks = lane & 15;      // 16-way K split (interleaved k-pairs)

    const u64 *Wp = reinterpret_cast<const u64 *>(Wsm) + (size_t)(w * 4) * 256;
    const u64 *hp = reinterpret_cast<const u64 *>(hsm) + (size_t)(a * 4) * 256;

    // This lane's single output after the halving reduction:
    const int j_out = j0g + w * 4 + (ks >> 2);
    const int b_out = b0 + a * 4 + (ks & 3);
    float *const out_base = out + (size_t)b_out * H_DIM + j_out;
    const float *const xin_base = g_xin + (size_t)b_out * H_DIM + j_out;

    for (int t = 0; t < T_DIM; t++) {
        // ---- load h for our 8 batches (4096 floats = 1024 float4) ----
        const float *hsrc = (t == 0) ? (h0 + (size_t)b0 * H_DIM)
                                     : (out + ((size_t)(t - 1) * B_DIM + b0) * H_DIM);
        const float4 *hs4 = reinterpret_cast<const float4 *>(hsrc);
        float4 *hd4 = reinterpret_cast<float4 *>(hsm);
        hd4[tid]       = __ldcg(&hs4[tid]);
        hd4[tid + 512] = __ldcg(&hs4[tid + 512]);

        // ---- prefetch this lane's xin value ----
        const float xpre = __ldcg(xin_base + (size_t)t * B_DIM * H_DIM);

        __syncthreads();  // hsm ready

        // ---- GEMM partials: acc[jj][bb] over this lane's 16 k-pairs ----
        u64 acc[4][4];
#pragma unroll
        for (int jj = 0; jj < 4; jj++)
#pragma unroll
            for (int bb = 0; bb < 4; bb++) acc[jj][bb] = 0ull;

#pragma unroll
        for (int i = 0; i < 16; i++) {
            const int kp = i * 16 + ks;
            u64 wr[4], hr[4];
#pragma unroll
            for (int jj = 0; jj < 4; jj++) wr[jj] = Wp[(size_t)jj * 256 + kp];
#pragma unroll
            for (int bb = 0; bb < 4; bb++) hr[bb] = hp[(size_t)bb * 256 + kp];
#pragma unroll
            for (int jj = 0; jj < 4; jj++)
#pragma unroll
                for (int bb = 0; bb < 4; bb++) fma2(acc[jj][bb], wr[jj], hr[bb]);
        }

        // ---- halving-tree reduction across the 16 ks lanes ----
        // v[] holds logical outputs v = jj*4+bb; after rounds o=8,4,2,1 the
        // lane with index ks ends owning logical output v = ks.
        float v[16];
#pragma unroll
        for (int jj = 0; jj < 4; jj++)
#pragma unroll
            for (int bb = 0; bb < 4; bb++) v[jj * 4 + bb] = f2sum(acc[jj][bb]);

#pragma unroll
        for (int o = 8; o >= 1; o >>= 1) {
            const bool hi = (ks & o) != 0;
#pragma unroll
            for (int i = 0; i < 16; i++) {   // only i < o iterations are live
                if (i < o) {
                    const float mine = hi ? v[i] : v[i + o];
                    const float keep = hi ? v[i + o] : v[i];
                    const float got = __shfl_xor_sync(0xffffffffu, mine, o);
                    v[i] = keep + got;
                }
            }
        }

        // ---- epilogue: one output per lane ----
        const float res = tanhf(v[0] + xpre);
        __stcg(out_base + (size_t)t * B_DIM * H_DIM, res);

        // ---- cluster barrier: publish out[t]; also covers the hsm WAR
        //      hazard (full execution barrier for every thread in cluster) ----
        asm volatile("barrier.cluster.arrive.aligned;" ::: "memory");
        asm volatile("barrier.cluster.wait.aligned;" ::: "memory");
    }
}

// ---------------------------------------------------------------------------
extern "C" void kernel_launch(void *const *d_in, const int *in_sizes, int n_in,
                              void *d_out, int out_size) {
    const float *x     = (const float *)d_in[0];
    const float *h     = (const float *)d_in[1];
    const float *W_in  = (const float *)d_in[2];
    const float *b_in  = (const float *)d_in[3];
    const float *W_lat = (const float *)d_in[4];
    const float *b_lat = (const float *)d_in[5];
    float *out = (float *)d_out;

    dim3 gx(H_DIM / 128, (T_DIM * B_DIM) / 128);   // (4, 512)
    xin_gemm<<<gx, 256>>>(x, W_in, b_in, b_lat);

    cudaFuncSetAttribute(rnn_scan, cudaFuncAttributeMaxDynamicSharedMemorySize,
                         SMEM_SCAN_FLOATS * (int)sizeof(float));
    rnn_scan<<<B_DIM, 512, SMEM_SCAN_FLOATS * sizeof(float)>>>(h, W_lat, out);
}

// round 5
// speedup vs baseline: 1.1772x; 1.1772x over previous
#include <cuda_runtime.h>
#include <cuda_bf16.h>
#include <math.h>
#include <cstdint>
#include <cstddef>

#define T_DIM 512
#define B_DIM 128
#define D_DIM 256
#define H_DIM 512

typedef unsigned long long u64;

// Scratch for precomputed input projection (+ biases). __device__ global =
// the sanctioned allocation-free scratch mechanism.
__device__ float g_xin[(size_t)T_DIM * B_DIM * H_DIM];

__device__ __forceinline__ void fma2(u64 &acc, u64 a, u64 b) {
    asm("fma.rn.f32x2 %0, %1, %2, %0;" : "+l"(acc) : "l"(a), "l"(b));
}
__device__ __forceinline__ float f2sum(u64 v) {
    float2 f = *reinterpret_cast<float2 *>(&v);
    return f.x + f.y;
}
__device__ __forceinline__ uint32_t smem_u32(const void *p) {
    uint32_t a;
    asm("{ .reg .u64 t; cvta.to.shared.u64 t, %1; cvt.u32.u64 %0, t; }" : "=r"(a) : "l"(p));
    return a;
}
__device__ __forceinline__ uint32_t mapa_u32(uint32_t addr, uint32_t rank) {
    uint32_t r;
    asm("mapa.shared::cluster.u32 %0, %1, %2;" : "=r"(r) : "r"(addr), "r"(rank));
    return r;
}
__device__ __forceinline__ void mbar_init(uint32_t a, uint32_t cnt) {
    asm volatile("mbarrier.init.shared.b64 [%0], %1;" :: "r"(a), "r"(cnt) : "memory");
}
__device__ __forceinline__ void mbar_expect_tx(uint32_t a, uint32_t tx) {
    asm volatile("mbarrier.arrive.expect_tx.shared.b64 _, [%0], %1;" :: "r"(a), "r"(tx) : "memory");
}
__device__ __forceinline__ void mbar_wait(uint32_t a, uint32_t parity) {
    uint32_t done;
    asm volatile(
        "{\n\t.reg .pred p;\n\t"
        "mbarrier.try_wait.parity.acquire.cta.shared::cta.b64 p, [%1], %2;\n\t"
        "selp.b32 %0, 1, 0, p;\n\t}"
        : "=r"(done) : "r"(a), "r"(parity) : "memory");
    if (!done) {
        asm volatile(
            "{\n\t.reg .pred P1;\n\t"
            "W_%=:\n\t"
            "mbarrier.try_wait.parity.acquire.cta.shared::cta.b64 P1, [%0], %1, 0x989680;\n\t"
            "@P1 bra.uni D_%=;\n\t"
            "bra.uni W_%=;\n\t"
            "D_%=:\n\t}"
            :: "r"(a), "r"(parity) : "memory");
    }
}
__device__ __forceinline__ void dsmem_bulk(uint32_t dst_cluster, uint32_t src_cta,
                                           uint32_t bytes, uint32_t mbar_cluster) {
    asm volatile(
        "cp.async.bulk.shared::cluster.shared::cta.mbarrier::complete_tx::bytes "
        "[%0], [%1], %2, [%3];"
        :: "r"(dst_cluster), "r"(src_cta), "r"(bytes), "r"(mbar_cluster) : "memory");
}

// ---------------------------------------------------------------------------
// Kernel 1: xin[t,b,n] = x[t,b,:] . W_in[n,:] + b_in[n] + b_lat[n]
// Unchanged from R2/R3 (known good, ~10% of runtime).
// ---------------------------------------------------------------------------
__global__ void __launch_bounds__(256, 1)
xin_gemm(const float *__restrict__ x, const float *__restrict__ W_in,
         const float *__restrict__ b_in, const float *__restrict__ b_lat) {
    __shared__ float As[128 * 16];
    __shared__ float Bs[128 * 18];

    const int tid = threadIdx.x;
    const int tx = tid & 15;
    const int ty = tid >> 4;
    const int m0 = blockIdx.y * 128;
    const int n0 = blockIdx.x * 128;

    u64 acc[8][8];
#pragma unroll
    for (int i = 0; i < 8; i++)
#pragma unroll
        for (int j = 0; j < 8; j++) acc[i][j] = 0ull;

    for (int kc = 0; kc < D_DIM; kc += 16) {
        __syncthreads();
#pragma unroll
        for (int u = 0; u < 2; u++) {
            int idx = tid + u * 256;
            int row = idx >> 2, c4 = idx & 3;
            float4 v = *reinterpret_cast<const float4 *>(
                &x[(size_t)(m0 + row) * D_DIM + kc + c4 * 4]);
            *reinterpret_cast<float4 *>(&As[row * 16 + c4 * 4]) = v;
        }
#pragma unroll
        for (int u = 0; u < 4; u++) {
            int idx = tid + u * 256;
            int row = idx >> 3, cp = idx & 7;
            float2 v = *reinterpret_cast<const float2 *>(
                &W_in[(size_t)(n0 + row) * D_DIM + kc + cp * 2]);
            *reinterpret_cast<float2 *>(&Bs[row * 18 + cp * 2]) = v;
        }
        __syncthreads();

        const u64 *As2 = reinterpret_cast<const u64 *>(As);
        const u64 *Bs2 = reinterpret_cast<const u64 *>(Bs);
#pragma unroll
        for (int kp = 0; kp < 8; kp++) {
            u64 a2[8], b2[8];
#pragma unroll
            for (int i = 0; i < 8; i++) a2[i] = As2[(ty * 8 + i) * 8 + kp];
#pragma unroll
            for (int j = 0; j < 8; j++) b2[j] = Bs2[(tx + 16 * j) * 9 + kp];
#pragma unroll
            for (int i = 0; i < 8; i++)
#pragma unroll
                for (int j = 0; j < 8; j++) fma2(acc[i][j], a2[i], b2[j]);
        }
    }

#pragma unroll
    for (int j = 0; j < 8; j++) {
        int n = n0 + tx + 16 * j;
        float bias = __ldg(&b_in[n]) + __ldg(&b_lat[n]);
#pragma unroll
        for (int i = 0; i < 8; i++) {
            g_xin[(size_t)(m0 + ty * 8 + i) * H_DIM + n] = f2sum(acc[i][j]) + bias;
        }
    }
}

// ---------------------------------------------------------------------------
// Kernel 2: the scan. 16 clusters x 8 CTAs, 512 threads. NO cluster barriers
// in the loop, NO global h traffic: h is exchanged via DSMEM bulk copies with
// tx-counted mbarriers, double-buffered. CTA rank r owns j rows [r*64,r*64+64)
// with its W_lat slice resident in smem.
//
// smem layout (bytes):
//   [0,16)        mbar0 @0, mbar1 @8
//   [1024,5120)   stage: 2 buffers x 2048 (this CTA's 8b x 64j slice)
//   [8192,40960)  hbuf: 2 buffers x 16384, layout [rank][b][64j]
//   [40960,172032) Wsm: 64 x 512 floats
// ---------------------------------------------------------------------------
#define MB_OFF    0
#define STAGE_OFF 1024
#define HBUF_OFF  8192
#define W_OFF     40960
#define SMEM_SCAN_BYTES (W_OFF + 64 * 512 * 4)   // 172032

__global__ void __cluster_dims__(8, 1, 1) __launch_bounds__(512, 1)
rnn_scan(const float *__restrict__ h0, const float *__restrict__ W_lat,
         float *__restrict__ out) {
    extern __shared__ float smem[];
    const uint32_t sbase = smem_u32(smem);

    float *Wsm  = reinterpret_cast<float *>(reinterpret_cast<char *>(smem) + W_OFF);
    float *hbuf = reinterpret_cast<float *>(reinterpret_cast<char *>(smem) + HBUF_OFF);
    float *stg  = reinterpret_cast<float *>(reinterpret_cast<char *>(smem) + STAGE_OFF);

    const int tid = threadIdx.x;
    const int r = blockIdx.x & 7;   // cluster rank -> j-slice
    const int g = blockIdx.x >> 3;  // cluster id  -> batch group
    const int j0g = r * 64;
    const int b0 = g * 8;

    // mbarrier init: one arrival (the local expect_tx post) per phase.
    if (tid == 0) {
        mbar_init(sbase + MB_OFF + 0, 1);
        mbar_init(sbase + MB_OFF + 8, 1);
    }

    // W_lat rows [j0g, j0g+64) -> smem (once).
    {
        const float4 *src = reinterpret_cast<const float4 *>(W_lat + (size_t)j0g * H_DIM);
        float4 *dst = reinterpret_cast<float4 *>(Wsm);
#pragma unroll
        for (int u = 0; u < 16; u++) dst[tid + 512 * u] = src[tid + 512 * u];
    }

    // Preload h(-1) = h0 into hbuf[1], layout [rank][b][64j]: element (b,k)
    // at ((k>>6)*8 + b)*64 + (k&63).
    {
        float4 *dst = reinterpret_cast<float4 *>(hbuf + 4096);  // buffer 1
#pragma unroll
        for (int u = 0; u < 2; u++) {
            int q = tid + u * 512;          // float4 index 0..1023
            int rr = q >> 7;                // rank block
            int b  = (q >> 4) & 7;          // batch
            int j4 = q & 15;                // float4 within 64 j
            float4 v = *reinterpret_cast<const float4 *>(
                &h0[(size_t)(b0 + b) * H_DIM + rr * 64 + j4 * 4]);
            dst[q] = v;
        }
    }
    __syncthreads();
    // Everyone's mbarriers + buffers ready before any DSMEM traffic.
    asm volatile("barrier.cluster.arrive.aligned;" ::: "memory");
    asm volatile("barrier.cluster.wait.aligned;" ::: "memory");

    const int lane = tid & 31;
    const int w = tid >> 5;        // warp 0..15 -> j rows [w*4, w*4+4)
    const int a = lane >> 4;       // batch half
    const int ks = lane & 15;      // 16-way K split

    // This lane's single output after the halving reduction:
    const int jj_o = ks >> 2, bb_o = ks & 3;
    const int j_rel = w * 4 + jj_o;            // 0..63
    const int b_rel = a * 4 + bb_o;            // 0..7
    const int j_out = j0g + j_rel;
    const int b_out = b0 + b_rel;
    float *const out_base = out + (size_t)b_out * H_DIM + j_out;
    const float *const xin_base = g_xin + (size_t)b_out * H_DIM + j_out;

    typedef ulonglong2 u64x2;
    const u64x2 *W2 = reinterpret_cast<const u64x2 *>(Wsm);

    int par0 = 0, par1 = 0;

    for (int t = 0; t < T_DIM; t++) {
        // Post expect for incoming h(t) (consumed at t+1). Safe here: this
        // mbar's previous phase (h(t-2)) was consumed by this CTA at step t-1.
        if (tid == 0 && t < T_DIM - 1)
            mbar_expect_tx(sbase + MB_OFF + (t & 1) * 8, 16384u);

        // xin prefetch (independent of the wait).
        const float xpre = __ldcg(xin_base + (size_t)t * B_DIM * H_DIM);

        // Wait for h(t-1) (t=0: preloaded, cluster-synced).
        const int rbuf = (t - 1) & 1;
        if (t > 0) {
            if (rbuf == 0) { mbar_wait(sbase + MB_OFF + 0, par0); if (tid == 0) {} par0 ^= 1; }
            else           { mbar_wait(sbase + MB_OFF + 8, par1); par1 ^= 1; }
        }

        const u64x2 *H2 = reinterpret_cast<const u64x2 *>(hbuf + rbuf * 4096);

        // ---- GEMM partials: acc[jj][bb], this lane's 16-way K split ----
        u64 acc[4][4];
#pragma unroll
        for (int jj = 0; jj < 4; jj++)
#pragma unroll
            for (int bb = 0; bb < 4; bb++) acc[jj][bb] = 0ull;

#pragma unroll
        for (int i = 0; i < 8; i++) {
            const int kq = i * 16 + ks;     // k-quad index 0..127
            u64x2 wr[4], hr[4];
#pragma unroll
            for (int jj = 0; jj < 4; jj++) wr[jj] = W2[(w * 4 + jj) * 128 + kq];
#pragma unroll
            for (int bb = 0; bb < 4; bb++) hr[bb] = H2[(i * 8 + a * 4 + bb) * 16 + ks];
#pragma unroll
            for (int jj = 0; jj < 4; jj++)
#pragma unroll
                for (int bb = 0; bb < 4; bb++) {
                    fma2(acc[jj][bb], wr[jj].x, hr[bb].x);
                    fma2(acc[jj][bb], wr[jj].y, hr[bb].y);
                }
        }

        // ---- halving-tree reduction across the 16 ks lanes ----
        float v[16];
#pragma unroll
        for (int jj = 0; jj < 4; jj++)
#pragma unroll
            for (int bb = 0; bb < 4; bb++) v[jj * 4 + bb] = f2sum(acc[jj][bb]);

#pragma unroll
        for (int o = 8; o >= 1; o >>= 1) {
            const bool hi = (ks & o) != 0;
#pragma unroll
            for (int i = 0; i < 16; i++) {
                if (i < o) {
                    const float mine = hi ? v[i] : v[i + o];
                    const float keep = hi ? v[i + o] : v[i];
                    const float got = __shfl_xor_sync(0xffffffffu, mine, o);
                    v[i] = keep + got;
                }
            }
        }

        // ---- epilogue: one output per lane ----
        const float res = tanhf(v[0] + xpre);
        __stcg(out_base + (size_t)t * B_DIM * H_DIM, res);

        if (t < T_DIM - 1) {
            // Stage our 8b x 64j slice (double-buffered), then 8 bulk copies.
            stg[(t & 1) * 512 + b_rel * 64 + j_rel] = res;
            __syncthreads();
            if (tid < 8) {
                asm volatile("fence.proxy.async.shared::cta;" ::: "memory");
                const uint32_t src = sbase + STAGE_OFF + (t & 1) * 2048;
                const uint32_t dst_l = sbase + HBUF_OFF + (t & 1) * 16384 + r * 2048;
                const uint32_t mb_l  = sbase + MB_OFF + (t & 1) * 8;
                const uint32_t peer = (uint32_t)tid;
                dsmem_bulk(mapa_u32(dst_l, peer), src, 2048u, mapa_u32(mb_l, peer));
            }
        }
    }

    // smem lifetime safety for in-flight peer traffic.
    asm volatile("barrier.cluster.arrive.aligned;" ::: "memory");
    asm volatile("barrier.cluster.wait.aligned;" ::: "memory");
}

// ---------------------------------------------------------------------------
extern "C" void kernel_launch(void *const *d_in, const int *in_sizes, int n_in,
                              void *d_out, int out_size) {
    const float *x     = (const float *)d_in[0];
    const float *h     = (const float *)d_in[1];
    const float *W_in  = (const float *)d_in[2];
    const float *b_in  = (const float *)d_in[3];
    const float *W_lat = (const float *)d_in[4];
    const float *b_lat = (const float *)d_in[5];
    float *out = (float *)d_out;

    dim3 gx(H_DIM / 128, (T_DIM * B_DIM) / 128);   // (4, 512)
    xin_gemm<<<gx, 256>>>(x, W_in, b_in, b_lat);

    cudaFuncSetAttribute(rnn_scan, cudaFuncAttributeMaxDynamicSharedMemorySize,
                         SMEM_SCAN_BYTES);
    rnn_scan<<<B_DIM, 512, SMEM_SCAN_BYTES>>>(h, W_lat, out);
}

// round 6
// speedup vs baseline: 1.2268x; 1.0422x over previous
#include <cuda_runtime.h>
#include <cuda_bf16.h>
#include <math.h>
#include <cstdint>
#include <cstddef>

#define T_DIM 512
#define B_DIM 128
#define D_DIM 256
#define H_DIM 512

typedef unsigned long long u64;
typedef ulonglong2 u64x2;

// Scratch for precomputed input projection (+ biases). __device__ global =
// the sanctioned allocation-free scratch mechanism.
__device__ float g_xin[(size_t)T_DIM * B_DIM * H_DIM];

__device__ __forceinline__ void fma2(u64 &acc, u64 a, u64 b) {
    asm("fma.rn.f32x2 %0, %1, %2, %0;" : "+l"(acc) : "l"(a), "l"(b));
}
__device__ __forceinline__ float f2sum(u64 v) {
    float2 f = *reinterpret_cast<float2 *>(&v);
    return f.x + f.y;
}
__device__ __forceinline__ uint32_t smem_u32(const void *p) {
    uint32_t a;
    asm("{ .reg .u64 t; cvta.to.shared.u64 t, %1; cvt.u32.u64 %0, t; }" : "=r"(a) : "l"(p));
    return a;
}
__device__ __forceinline__ uint32_t mapa_u32(uint32_t addr, uint32_t rank) {
    uint32_t r;
    asm("mapa.shared::cluster.u32 %0, %1, %2;" : "=r"(r) : "r"(addr), "r"(rank));
    return r;
}
__device__ __forceinline__ void mbar_init(uint32_t a, uint32_t cnt) {
    asm volatile("mbarrier.init.shared.b64 [%0], %1;" :: "r"(a), "r"(cnt) : "memory");
}
__device__ __forceinline__ void mbar_expect_tx(uint32_t a, uint32_t tx) {
    asm volatile("mbarrier.arrive.expect_tx.shared.b64 _, [%0], %1;" :: "r"(a), "r"(tx) : "memory");
}
__device__ __forceinline__ void mbar_wait(uint32_t a, uint32_t parity) {
    uint32_t done;
    asm volatile(
        "{\n\t.reg .pred p;\n\t"
        "mbarrier.try_wait.parity.acquire.cta.shared::cta.b64 p, [%1], %2;\n\t"
        "selp.b32 %0, 1, 0, p;\n\t}"
        : "=r"(done) : "r"(a), "r"(parity) : "memory");
    if (!done) {
        asm volatile(
            "{\n\t.reg .pred P1;\n\t"
            "W_%=:\n\t"
            "mbarrier.try_wait.parity.acquire.cta.shared::cta.b64 P1, [%0], %1, 0x989680;\n\t"
            "@P1 bra.uni D_%=;\n\t"
            "bra.uni W_%=;\n\t"
            "D_%=:\n\t}"
            :: "r"(a), "r"(parity) : "memory");
    }
}
__device__ __forceinline__ void dsmem_bulk(uint32_t dst_cluster, uint32_t src_cta,
                                           uint32_t bytes, uint32_t mbar_cluster) {
    asm volatile(
        "cp.async.bulk.shared::cluster.shared::cta.mbarrier::complete_tx::bytes "
        "[%0], [%1], %2, [%3];"
        :: "r"(dst_cluster), "r"(src_cta), "r"(bytes), "r"(mbar_cluster) : "memory");
}

// ---------------------------------------------------------------------------
// Kernel 1: xin[t,b,n] = x[t,b,:] . W_in[n,:] + b_in[n] + b_lat[n]
// Now double-buffered (register-staged, one __syncthreads per k-tile).
// ---------------------------------------------------------------------------
__global__ void __launch_bounds__(256, 1)
xin_gemm(const float *__restrict__ x, const float *__restrict__ W_in,
         const float *__restrict__ b_in, const float *__restrict__ b_lat) {
    __shared__ float As[2][128 * 16];
    __shared__ float Bs[2][128 * 18];

    const int tid = threadIdx.x;
    const int tx = tid & 15;
    const int ty = tid >> 4;
    const int m0 = blockIdx.y * 128;
    const int n0 = blockIdx.x * 128;

    // Per-thread staging slots
    const int a_row0 = tid >> 2,  a_c4 = tid & 3;              // +64 rows per u
    const int b_row0 = tid >> 3,  b_cp = tid & 7;              // +32 rows per u

    float4 ra[2];
    float2 rb[4];

    // Prologue: load k-tile 0 into regs, store to buffer 0.
#pragma unroll
    for (int u = 0; u < 2; u++)
        ra[u] = *reinterpret_cast<const float4 *>(
            &x[(size_t)(m0 + a_row0 + u * 64) * D_DIM + a_c4 * 4]);
#pragma unroll
    for (int u = 0; u < 4; u++)
        rb[u] = *reinterpret_cast<const float2 *>(
            &W_in[(size_t)(n0 + b_row0 + u * 32) * D_DIM + b_cp * 2]);
#pragma unroll
    for (int u = 0; u < 2; u++)
        *reinterpret_cast<float4 *>(&As[0][(a_row0 + u * 64) * 16 + a_c4 * 4]) = ra[u];
#pragma unroll
    for (int u = 0; u < 4; u++)
        *reinterpret_cast<float2 *>(&Bs[0][(b_row0 + u * 32) * 18 + b_cp * 2]) = rb[u];
    __syncthreads();

    u64 acc[8][8];
#pragma unroll
    for (int i = 0; i < 8; i++)
#pragma unroll
        for (int j = 0; j < 8; j++) acc[i][j] = 0ull;

#pragma unroll 1
    for (int it = 0; it < 16; it++) {
        const int cur = it & 1;
        // Issue next tile's global loads (latency overlapped with compute).
        if (it < 15) {
            const int kc = (it + 1) * 16;
#pragma unroll
            for (int u = 0; u < 2; u++)
                ra[u] = *reinterpret_cast<const float4 *>(
                    &x[(size_t)(m0 + a_row0 + u * 64) * D_DIM + kc + a_c4 * 4]);
#pragma unroll
            for (int u = 0; u < 4; u++)
                rb[u] = *reinterpret_cast<const float2 *>(
                    &W_in[(size_t)(n0 + b_row0 + u * 32) * D_DIM + kc + b_cp * 2]);
        }

        const u64 *As2 = reinterpret_cast<const u64 *>(As[cur]);
        const u64 *Bs2 = reinterpret_cast<const u64 *>(Bs[cur]);
#pragma unroll
        for (int kp = 0; kp < 8; kp++) {
            u64 a2[8], b2[8];
#pragma unroll
            for (int i = 0; i < 8; i++) a2[i] = As2[(ty * 8 + i) * 8 + kp];
#pragma unroll
            for (int j = 0; j < 8; j++) b2[j] = Bs2[(tx + 16 * j) * 9 + kp];
#pragma unroll
            for (int i = 0; i < 8; i++)
#pragma unroll
                for (int j = 0; j < 8; j++) fma2(acc[i][j], a2[i], b2[j]);
        }

        if (it < 15) {
            const int nxt = cur ^ 1;
            // Safe: all threads passed the previous sync, so nobody is still
            // computing on buffer `nxt` (used two iterations ago).
#pragma unroll
            for (int u = 0; u < 2; u++)
                *reinterpret_cast<float4 *>(&As[nxt][(a_row0 + u * 64) * 16 + a_c4 * 4]) = ra[u];
#pragma unroll
            for (int u = 0; u < 4; u++)
                *reinterpret_cast<float2 *>(&Bs[nxt][(b_row0 + u * 32) * 18 + b_cp * 2]) = rb[u];
            __syncthreads();
        }
    }

#pragma unroll
    for (int j = 0; j < 8; j++) {
        int n = n0 + tx + 16 * j;
        float bias = __ldg(&b_in[n]) + __ldg(&b_lat[n]);
#pragma unroll
        for (int i = 0; i < 8; i++) {
            g_xin[(size_t)(m0 + ty * 8 + i) * H_DIM + n] = f2sum(acc[i][j]) + bias;
        }
    }
}

// ---------------------------------------------------------------------------
// Kernel 2: the scan. 16 clusters x 8 CTAs, 512 threads. h is exchanged via
// DSMEM bulk copies, but consumption is PIPELINED: the GEMM walks h in 8
// rank-chunks of 64 k, starting with the locally-produced chunk (rank r) —
// no wait — then waits on two mbar groups: A (ranks r+1..r+3) and B
// (r+4..r+7). Transfers overlap the first chunks' compute.
//
// smem layout (bytes):
//   [0,32)         mbars: buf0A@0 buf0B@8 buf1A@16 buf1B@24
//   [1024,5120)    stage: 2 x 2048 (this CTA's 8b x 64j slice)
//   [8192,40960)   hbuf: 2 x 16384, layout [rank][b][64k]
//   [40960,172032) Wsm: 64 x 512 floats
// ---------------------------------------------------------------------------
#define MB_OFF    0
#define STAGE_OFF 1024
#define HBUF_OFF  8192
#define W_OFF     40960
#define SMEM_SCAN_BYTES (W_OFF + 64 * 512 * 4)   // 172032

__global__ void __cluster_dims__(8, 1, 1) __launch_bounds__(512, 1)
rnn_scan(const float *__restrict__ h0, const float *__restrict__ W_lat,
         float *__restrict__ out) {
    extern __shared__ float smem[];
    const uint32_t sbase = smem_u32(smem);

    float *Wsm  = reinterpret_cast<float *>(reinterpret_cast<char *>(smem) + W_OFF);
    float *hbuf = reinterpret_cast<float *>(reinterpret_cast<char *>(smem) + HBUF_OFF);
    float *stg  = reinterpret_cast<float *>(reinterpret_cast<char *>(smem) + STAGE_OFF);

    const int tid = threadIdx.x;
    const int r = blockIdx.x & 7;   // cluster rank -> j-slice
    const int g = blockIdx.x >> 3;  // cluster id  -> batch group
    const int j0g = r * 64;
    const int b0 = g * 8;

    if (tid < 4) mbar_init(sbase + MB_OFF + tid * 8, 1);

    // W_lat rows [j0g, j0g+64) -> smem (once).
    {
        const float4 *src = reinterpret_cast<const float4 *>(W_lat + (size_t)j0g * H_DIM);
        float4 *dst = reinterpret_cast<float4 *>(Wsm);
#pragma unroll
        for (int u = 0; u < 16; u++) dst[tid + 512 * u] = src[tid + 512 * u];
    }

    // Preload h(-1) = h0 into hbuf buffer 1, layout [rank][b][64k].
    {
        float4 *dst = reinterpret_cast<float4 *>(hbuf + 4096);  // buffer 1
#pragma unroll
        for (int u = 0; u < 2; u++) {
            int q = tid + u * 512;          // float4 index 0..1023
            int rr = q >> 7;                // rank block
            int b  = (q >> 4) & 7;          // batch
            int j4 = q & 15;                // float4 within 64 k
            dst[q] = *reinterpret_cast<const float4 *>(
                &h0[(size_t)(b0 + b) * H_DIM + rr * 64 + j4 * 4]);
        }
    }
    __syncthreads();
    // All CTAs' mbars + buffers ready before any DSMEM traffic.
    asm volatile("barrier.cluster.arrive.aligned;" ::: "memory");
    asm volatile("barrier.cluster.wait.aligned;" ::: "memory");

    const int lane = tid & 31;
    const int w = tid >> 5;        // warp 0..15 -> j rows [w*4, w*4+4)
    const int a = lane >> 4;       // batch half
    const int ks = lane & 15;      // 16-way K split

    // This lane's single output after the halving reduction:
    const int jj_o = ks >> 2, bb_o = ks & 3;
    const int j_rel = w * 4 + jj_o;            // 0..63
    const int b_rel = a * 4 + bb_o;            // 0..7
    const int j_out = j0g + j_rel;
    const int b_out = b0 + b_rel;
    float *const out_base = out + (size_t)b_out * H_DIM + j_out;
    const float *const xin_base = g_xin + (size_t)b_out * H_DIM + j_out;

    const u64x2 *W2 = reinterpret_cast<const u64x2 *>(Wsm);

    int parA[2] = {0, 0}, parB[2] = {0, 0};

    for (int t = 0; t < T_DIM; t++) {
        // Post expects for incoming h(t) (consumed at t+1). Earliest possible
        // arrival is a full peer GEMM away — safely after this.
        if (tid == 0 && t < T_DIM - 1) {
            mbar_expect_tx(sbase + MB_OFF + (t & 1) * 16 + 0, 3 * 2048u);
            mbar_expect_tx(sbase + MB_OFF + (t & 1) * 16 + 8, 4 * 2048u);
        }

        const float xpre = __ldcg(xin_base + (size_t)t * B_DIM * H_DIM);

        const int rb = (t - 1) & 1;    // buffer holding h(t-1); t=0 -> preload
        const u64x2 *H2 = reinterpret_cast<const u64x2 *>(hbuf + rb * 4096);

        u64 acc[4][4];
#pragma unroll
        for (int jj = 0; jj < 4; jj++)
#pragma unroll
            for (int bb = 0; bb < 4; bb++) acc[jj][bb] = 0ull;

        auto do_chunk = [&](int rank) {
            u64x2 wr[4], hr[4];
#pragma unroll
            for (int jj = 0; jj < 4; jj++) wr[jj] = W2[(w * 4 + jj) * 128 + rank * 16 + ks];
#pragma unroll
            for (int bb = 0; bb < 4; bb++) hr[bb] = H2[(rank * 8 + a * 4 + bb) * 16 + ks];
#pragma unroll
            for (int jj = 0; jj < 4; jj++)
#pragma unroll
                for (int bb = 0; bb < 4; bb++) {
                    fma2(acc[jj][bb], wr[jj].x, hr[bb].x);
                    fma2(acc[jj][bb], wr[jj].y, hr[bb].y);
                }
        };

        // Own chunk first (produced locally last step — no wait).
        do_chunk(r);
        if (t > 0) { mbar_wait(sbase + MB_OFF + rb * 16 + 0, parA[rb]); parA[rb] ^= 1; }
        do_chunk((r + 1) & 7);
        do_chunk((r + 2) & 7);
        do_chunk((r + 3) & 7);
        if (t > 0) { mbar_wait(sbase + MB_OFF + rb * 16 + 8, parB[rb]); parB[rb] ^= 1; }
        do_chunk((r + 4) & 7);
        do_chunk((r + 5) & 7);
        do_chunk((r + 6) & 7);
        do_chunk((r + 7) & 7);

        // ---- halving-tree reduction across the 16 ks lanes ----
        float v[16];
#pragma unroll
        for (int jj = 0; jj < 4; jj++)
#pragma unroll
            for (int bb = 0; bb < 4; bb++) v[jj * 4 + bb] = f2sum(acc[jj][bb]);

#pragma unroll
        for (int o = 8; o >= 1; o >>= 1) {
            const bool hi = (ks & o) != 0;
#pragma unroll
            for (int i = 0; i < 16; i++) {
                if (i < o) {
                    const float mine = hi ? v[i] : v[i + o];
                    const float keep = hi ? v[i + o] : v[i];
                    const float got = __shfl_xor_sync(0xffffffffu, mine, o);
                    v[i] = keep + got;
                }
            }
        }

        // ---- epilogue: fast tanh (abs err ~1e-7, saturates to +-1) ----
        const float s = v[0] + xpre;
        const float e = __expf(2.0f * s);
        const float res = 1.0f - __fdividef(2.0f, e + 1.0f);
        __stcg(out_base + (size_t)t * B_DIM * H_DIM, res);

        if (t < T_DIM - 1) {
            // Own slice: local hbuf (self) + stage (for the 7 peers).
            stg[(t & 1) * 512 + b_rel * 64 + j_rel] = res;
            hbuf[(t & 1) * 4096 + (r * 8 + b_rel) * 64 + j_rel] = res;
            __syncthreads();
            if (tid < 7) {
                asm volatile("fence.proxy.async.shared::cta;" ::: "memory");
                const uint32_t peer = (uint32_t)((r + 1 + tid) & 7);
                // Consumption position of our chunk on that peer: c = 7 - tid.
                // c in 4..7 -> group B (offset 8), c in 1..3 -> group A.
                const uint32_t grp_off = (tid < 4) ? 8u : 0u;
                const uint32_t src  = sbase + STAGE_OFF + (t & 1) * 2048;
                const uint32_t dst  = sbase + HBUF_OFF + (t & 1) * 16384 + r * 2048;
                const uint32_t mb   = sbase + MB_OFF + (t & 1) * 16 + grp_off;
                dsmem_bulk(mapa_u32(dst, peer), src, 2048u, mapa_u32(mb, peer));
            }
        }
    }

    // smem lifetime safety for in-flight peer traffic.
    asm volatile("barrier.cluster.arrive.aligned;" ::: "memory");
    asm volatile("barrier.cluster.wait.aligned;" ::: "memory");
}

// ---------------------------------------------------------------------------
extern "C" void kernel_launch(void *const *d_in, const int *in_sizes, int n_in,
                              void *d_out, int out_size) {
    const float *x     = (const float *)d_in[0];
    const float *h     = (const float *)d_in[1];
    const float *W_in  = (const float *)d_in[2];
    const float *b_in  = (const float *)d_in[3];
    const float *W_lat = (const float *)d_in[4];
    const float *b_lat = (const float *)d_in[5];
    float *out = (float *)d_out;

    dim3 gx(H_DIM / 128, (T_DIM * B_DIM) / 128);   // (4, 512)
    xin_gemm<<<gx, 256>>>(x, W_in, b_in, b_lat);

    cudaFuncSetAttribute(rnn_scan, cudaFuncAttributeMaxDynamicSharedMemorySize,
                         SMEM_SCAN_BYTES);
    rnn_scan<<<B_DIM, 512, SMEM_SCAN_BYTES>>>(h, W_lat, out);
}

// round 7
// speedup vs baseline: 1.2450x; 1.0148x over previous
#include <cuda_runtime.h>
#include <cuda_bf16.h>
#include <math.h>
#include <cstdint>
#include <cstddef>

#define T_DIM 512
#define B_DIM 128
#define D_DIM 256
#define H_DIM 512

typedef unsigned long long u64;
typedef ulonglong2 u64x2;

// Scratch for precomputed input projection (+ biases). __device__ global =
// the sanctioned allocation-free scratch mechanism.
__device__ float g_xin[(size_t)T_DIM * B_DIM * H_DIM];

__device__ __forceinline__ void fma2(u64 &acc, u64 a, u64 b) {
    asm("fma.rn.f32x2 %0, %1, %2, %0;" : "+l"(acc) : "l"(a), "l"(b));
}
__device__ __forceinline__ float f2sum(u64 v) {
    float2 f = *reinterpret_cast<float2 *>(&v);
    return f.x + f.y;
}
__device__ __forceinline__ uint32_t smem_u32(const void *p) {
    uint32_t a;
    asm("{ .reg .u64 t; cvta.to.shared.u64 t, %1; cvt.u32.u64 %0, t; }" : "=r"(a) : "l"(p));
    return a;
}
__device__ __forceinline__ uint32_t mapa_u32(uint32_t addr, uint32_t rank) {
    uint32_t r;
    asm("mapa.shared::cluster.u32 %0, %1, %2;" : "=r"(r) : "r"(addr), "r"(rank));
    return r;
}
__device__ __forceinline__ void mbar_init(uint32_t a, uint32_t cnt) {
    asm volatile("mbarrier.init.shared.b64 [%0], %1;" :: "r"(a), "r"(cnt) : "memory");
}
__device__ __forceinline__ void mbar_expect_tx(uint32_t a, uint32_t tx) {
    asm volatile("mbarrier.arrive.expect_tx.shared.b64 _, [%0], %1;" :: "r"(a), "r"(tx) : "memory");
}
__device__ __forceinline__ void mbar_wait(uint32_t a, uint32_t parity) {
    uint32_t done;
    asm volatile(
        "{\n\t.reg .pred p;\n\t"
        "mbarrier.try_wait.parity.acquire.cta.shared::cta.b64 p, [%1], %2;\n\t"
        "selp.b32 %0, 1, 0, p;\n\t}"
        : "=r"(done) : "r"(a), "r"(parity) : "memory");
    if (!done) {
        asm volatile(
            "{\n\t.reg .pred P1;\n\t"
            "W_%=:\n\t"
            "mbarrier.try_wait.parity.acquire.cta.shared::cta.b64 P1, [%0], %1, 0x989680;\n\t"
            "@P1 bra.uni D_%=;\n\t"
            "bra.uni W_%=;\n\t"
            "D_%=:\n\t}"
            :: "r"(a), "r"(parity) : "memory");
    }
}
__device__ __forceinline__ void dsmem_bulk(uint32_t dst_cluster, uint32_t src_cta,
                                           uint32_t bytes, uint32_t mbar_cluster) {
    asm volatile(
        "cp.async.bulk.shared::cluster.shared::cta.mbarrier::complete_tx::bytes "
        "[%0], [%1], %2, [%3];"
        :: "r"(dst_cluster), "r"(src_cta), "r"(bytes), "r"(mbar_cluster) : "memory");
}

// ---------------------------------------------------------------------------
// Kernel 1: xin[t,b,n] = x[t,b,:] . W_in[n,:] + b_in[n] + b_lat[n]
// Double-buffered fp32 tiled GEMM (unchanged from R5).
// ---------------------------------------------------------------------------
__global__ void __launch_bounds__(256, 1)
xin_gemm(const float *__restrict__ x, const float *__restrict__ W_in,
         const float *__restrict__ b_in, const float *__restrict__ b_lat) {
    __shared__ float As[2][128 * 16];
    __shared__ float Bs[2][128 * 18];

    const int tid = threadIdx.x;
    const int tx = tid & 15;
    const int ty = tid >> 4;
    const int m0 = blockIdx.y * 128;
    const int n0 = blockIdx.x * 128;

    const int a_row0 = tid >> 2,  a_c4 = tid & 3;
    const int b_row0 = tid >> 3,  b_cp = tid & 7;

    float4 ra[2];
    float2 rb[4];

#pragma unroll
    for (int u = 0; u < 2; u++)
        ra[u] = *reinterpret_cast<const float4 *>(
            &x[(size_t)(m0 + a_row0 + u * 64) * D_DIM + a_c4 * 4]);
#pragma unroll
    for (int u = 0; u < 4; u++)
        rb[u] = *reinterpret_cast<const float2 *>(
            &W_in[(size_t)(n0 + b_row0 + u * 32) * D_DIM + b_cp * 2]);
#pragma unroll
    for (int u = 0; u < 2; u++)
        *reinterpret_cast<float4 *>(&As[0][(a_row0 + u * 64) * 16 + a_c4 * 4]) = ra[u];
#pragma unroll
    for (int u = 0; u < 4; u++)
        *reinterpret_cast<float2 *>(&Bs[0][(b_row0 + u * 32) * 18 + b_cp * 2]) = rb[u];
    __syncthreads();

    u64 acc[8][8];
#pragma unroll
    for (int i = 0; i < 8; i++)
#pragma unroll
        for (int j = 0; j < 8; j++) acc[i][j] = 0ull;

#pragma unroll 1
    for (int it = 0; it < 16; it++) {
        const int cur = it & 1;
        if (it < 15) {
            const int kc = (it + 1) * 16;
#pragma unroll
            for (int u = 0; u < 2; u++)
                ra[u] = *reinterpret_cast<const float4 *>(
                    &x[(size_t)(m0 + a_row0 + u * 64) * D_DIM + kc + a_c4 * 4]);
#pragma unroll
            for (int u = 0; u < 4; u++)
                rb[u] = *reinterpret_cast<const float2 *>(
                    &W_in[(size_t)(n0 + b_row0 + u * 32) * D_DIM + kc + b_cp * 2]);
        }

        const u64 *As2 = reinterpret_cast<const u64 *>(As[cur]);
        const u64 *Bs2 = reinterpret_cast<const u64 *>(Bs[cur]);
#pragma unroll
        for (int kp = 0; kp < 8; kp++) {
            u64 a2[8], b2[8];
#pragma unroll
            for (int i = 0; i < 8; i++) a2[i] = As2[(ty * 8 + i) * 8 + kp];
#pragma unroll
            for (int j = 0; j < 8; j++) b2[j] = Bs2[(tx + 16 * j) * 9 + kp];
#pragma unroll
            for (int i = 0; i < 8; i++)
#pragma unroll
                for (int j = 0; j < 8; j++) fma2(acc[i][j], a2[i], b2[j]);
        }

        if (it < 15) {
            const int nxt = cur ^ 1;
#pragma unroll
            for (int u = 0; u < 2; u++)
                *reinterpret_cast<float4 *>(&As[nxt][(a_row0 + u * 64) * 16 + a_c4 * 4]) = ra[u];
#pragma unroll
            for (int u = 0; u < 4; u++)
                *reinterpret_cast<float2 *>(&Bs[nxt][(b_row0 + u * 32) * 18 + b_cp * 2]) = rb[u];
            __syncthreads();
        }
    }

#pragma unroll
    for (int j = 0; j < 8; j++) {
        int n = n0 + tx + 16 * j;
        float bias = __ldg(&b_in[n]) + __ldg(&b_lat[n]);
#pragma unroll
        for (int i = 0; i < 8; i++) {
            g_xin[(size_t)(m0 + ty * 8 + i) * H_DIM + n] = f2sum(acc[i][j]) + bias;
        }
    }
}

// ---------------------------------------------------------------------------
// Kernel 2: the scan. 16 clusters x 8 CTAs, 512 threads. DSMEM push exchange
// with ARRIVAL-ORDERED consumption: producer P's bulk copies drain serially
// (tid k -> peer P+1+k), so consumer C receives rank C-1's slice first and
// rank C-7's last. Chunks are consumed r, r-1, ..., r-7 so need-order ==
// arrival-order. Group A = positions 1-2 (tx 4KB), waited after the own
// chunk; group B = positions 3-7 (tx 10KB), waited two chunks later.
// xin value prefetched one full step ahead in a register.
//
// smem layout (bytes):
//   [0,32)         mbars: buf0A@0 buf0B@8 buf1A@16 buf1B@24
//   [1024,33792)   hbuf: 2 x 16384, layout [rank][b][64k]
//   [33792,164864) Wsm: 64 x 512 floats
// ---------------------------------------------------------------------------
#define MB_OFF    0
#define HBUF_OFF  1024
#define W_OFF     33792
#define SMEM_SCAN_BYTES (W_OFF + 64 * 512 * 4)   // 164864

__global__ void __cluster_dims__(8, 1, 1) __launch_bounds__(512, 1)
rnn_scan(const float *__restrict__ h0, const float *__restrict__ W_lat,
         float *__restrict__ out) {
    extern __shared__ float smem[];
    const uint32_t sbase = smem_u32(smem);

    float *hbuf = reinterpret_cast<float *>(reinterpret_cast<char *>(smem) + HBUF_OFF);
    float *Wsm  = reinterpret_cast<float *>(reinterpret_cast<char *>(smem) + W_OFF);

    const int tid = threadIdx.x;
    const int r = blockIdx.x & 7;   // cluster rank -> j-slice
    const int g = blockIdx.x >> 3;  // cluster id  -> batch group
    const int j0g = r * 64;
    const int b0 = g * 8;

    if (tid < 4) mbar_init(sbase + MB_OFF + tid * 8, 1);

    // W_lat rows [j0g, j0g+64) -> smem (once).
    {
        const float4 *src = reinterpret_cast<const float4 *>(W_lat + (size_t)j0g * H_DIM);
        float4 *dst = reinterpret_cast<float4 *>(Wsm);
#pragma unroll
        for (int u = 0; u < 16; u++) dst[tid + 512 * u] = src[tid + 512 * u];
    }

    // Preload h(-1) = h0 into hbuf buffer 1, layout [rank][b][64k].
    {
        float4 *dst = reinterpret_cast<float4 *>(hbuf + 4096);  // buffer 1
#pragma unroll
        for (int u = 0; u < 2; u++) {
            int q = tid + u * 512;          // float4 index 0..1023
            int rr = q >> 7;                // rank block
            int b  = (q >> 4) & 7;          // batch
            int j4 = q & 15;                // float4 within 64 k
            dst[q] = *reinterpret_cast<const float4 *>(
                &h0[(size_t)(b0 + b) * H_DIM + rr * 64 + j4 * 4]);
        }
    }
    __syncthreads();
    // All CTAs' mbars + buffers ready before any DSMEM traffic.
    asm volatile("barrier.cluster.arrive.aligned;" ::: "memory");
    asm volatile("barrier.cluster.wait.aligned;" ::: "memory");

    const int lane = tid & 31;
    const int w = tid >> 5;        // warp 0..15 -> j rows [w*4, w*4+4)
    const int a = lane >> 4;       // batch half
    const int ks = lane & 15;      // 16-way K split

    // This lane's single output after the halving reduction:
    const int jj_o = ks >> 2, bb_o = ks & 3;
    const int j_rel = w * 4 + jj_o;            // 0..63
    const int b_rel = a * 4 + bb_o;            // 0..7
    const int j_out = j0g + j_rel;
    const int b_out = b0 + b_rel;
    float *const out_base = out + (size_t)b_out * H_DIM + j_out;
    const float *const xin_base = g_xin + (size_t)b_out * H_DIM + j_out;

    const u64x2 *W2 = reinterpret_cast<const u64x2 *>(Wsm);

    int parA[2] = {0, 0}, parB[2] = {0, 0};

    // xin prefetch, one full step of slack.
    float xpre = __ldcg(xin_base);

    for (int t = 0; t < T_DIM; t++) {
        // Prefetch next step's xin (consumed next iteration).
        float xnext = 0.0f;
        if (t + 1 < T_DIM)
            xnext = __ldcg(xin_base + (size_t)(t + 1) * B_DIM * H_DIM);

        // Post expects for incoming h(t) (consumed at t+1). Earliest possible
        // arrival is a full peer step away — safely after this.
        if (tid == 0 && t < T_DIM - 1) {
            mbar_expect_tx(sbase + MB_OFF + (t & 1) * 16 + 0, 2 * 2048u);   // A
            mbar_expect_tx(sbase + MB_OFF + (t & 1) * 16 + 8, 5 * 2048u);   // B
        }

        const int rb = (t - 1) & 1;    // buffer holding h(t-1); t=0 -> preload
        const u64x2 *H2 = reinterpret_cast<const u64x2 *>(hbuf + rb * 4096);

        u64 acc[4][4];
#pragma unroll
        for (int jj = 0; jj < 4; jj++)
#pragma unroll
            for (int bb = 0; bb < 4; bb++) acc[jj][bb] = 0ull;

        auto do_chunk = [&](int rank) {
            u64x2 wr[4], hr[4];
#pragma unroll
            for (int jj = 0; jj < 4; jj++) wr[jj] = W2[(w * 4 + jj) * 128 + rank * 16 + ks];
#pragma unroll
            for (int bb = 0; bb < 4; bb++) hr[bb] = H2[(rank * 8 + a * 4 + bb) * 16 + ks];
#pragma unroll
            for (int jj = 0; jj < 4; jj++)
#pragma unroll
                for (int bb = 0; bb < 4; bb++) {
                    fma2(acc[jj][bb], wr[jj].x, hr[bb].x);
                    fma2(acc[jj][bb], wr[jj].y, hr[bb].y);
                }
        };

        // Own chunk first (produced locally last step — no wait), then peers
        // in ARRIVAL order r-1, r-2, ..., r-7.
        do_chunk(r);
        if (t > 0) { mbar_wait(sbase + MB_OFF + rb * 16 + 0, parA[rb]); parA[rb] ^= 1; }
        do_chunk((r + 7) & 7);
        do_chunk((r + 6) & 7);
        if (t > 0) { mbar_wait(sbase + MB_OFF + rb * 16 + 8, parB[rb]); parB[rb] ^= 1; }
        do_chunk((r + 5) & 7);
        do_chunk((r + 4) & 7);
        do_chunk((r + 3) & 7);
        do_chunk((r + 2) & 7);
        do_chunk((r + 1) & 7);

        // ---- halving-tree reduction across the 16 ks lanes ----
        float v[16];
#pragma unroll
        for (int jj = 0; jj < 4; jj++)
#pragma unroll
            for (int bb = 0; bb < 4; bb++) v[jj * 4 + bb] = f2sum(acc[jj][bb]);

#pragma unroll
        for (int o = 8; o >= 1; o >>= 1) {
            const bool hi = (ks & o) != 0;
#pragma unroll
            for (int i = 0; i < 16; i++) {
                if (i < o) {
                    const float mine = hi ? v[i] : v[i + o];
                    const float keep = hi ? v[i + o] : v[i];
                    const float got = __shfl_xor_sync(0xffffffffu, mine, o);
                    v[i] = keep + got;
                }
            }
        }

        // ---- epilogue: fast tanh (abs err ~1e-7, saturates to +-1) ----
        const float s = v[0] + xpre;
        const float e = __expf(2.0f * s);
        const float res = 1.0f - __fdividef(2.0f, e + 1.0f);
        __stcg(out_base + (size_t)t * B_DIM * H_DIM, res);
        xpre = xnext;

        if (t < T_DIM - 1) {
            // Own slice straight into local hbuf (contiguous 2KB rank block) —
            // doubles as the bulk-send source.
            hbuf[(t & 1) * 4096 + (r * 8 + b_rel) * 64 + j_rel] = res;
            __syncthreads();
            if (tid < 7) {
                asm volatile("fence.proxy.async.shared::cta;" ::: "memory");
                const uint32_t peer = (uint32_t)((r + 1 + tid) & 7);
                // Consumer position of our chunk on that peer = tid+1.
                // Positions 1-2 -> group A (offset 0), 3-7 -> group B (offset 8).
                const uint32_t grp_off = (tid < 2) ? 0u : 8u;
                const uint32_t src  = sbase + HBUF_OFF + (t & 1) * 16384 + r * 2048;
                const uint32_t mb   = sbase + MB_OFF + (t & 1) * 16 + grp_off;
                dsmem_bulk(mapa_u32(src, peer), src, 2048u, mapa_u32(mb, peer));
            }
        }
    }

    // smem lifetime safety for in-flight peer traffic.
    asm volatile("barrier.cluster.arrive.aligned;" ::: "memory");
    asm volatile("barrier.cluster.wait.aligned;" ::: "memory");
}

// ---------------------------------------------------------------------------
extern "C" void kernel_launch(void *const *d_in, const int *in_sizes, int n_in,
                              void *d_out, int out_size) {
    const float *x     = (const float *)d_in[0];
    const float *h     = (const float *)d_in[1];
    const float *W_in  = (const float *)d_in[2];
    const float *b_in  = (const float *)d_in[3];
    const float *W_lat = (const float *)d_in[4];
    const float *b_lat = (const float *)d_in[5];
    float *out = (float *)d_out;

    dim3 gx(H_DIM / 128, (T_DIM * B_DIM) / 128);   // (4, 512)
    xin_gemm<<<gx, 256>>>(x, W_in, b_in, b_lat);

    cudaFuncSetAttribute(rnn_scan, cudaFuncAttributeMaxDynamicSharedMemorySize,
                         SMEM_SCAN_BYTES);
    rnn_scan<<<B_DIM, 512, SMEM_SCAN_BYTES>>>(h, W_lat, out);
}

// round 10
// speedup vs baseline: 2.0609x; 1.6553x over previous
#include <cuda_runtime.h>
#include <cuda_bf16.h>
#include <math.h>
#include <cstdint>
#include <cstddef>

#define T_DIM 512
#define B_DIM 128
#define D_DIM 256
#define H_DIM 512

typedef unsigned long long u64;

// Scratch for precomputed input projection (+ biases). __device__ global =
// the sanctioned allocation-free scratch mechanism.
__device__ float g_xin[(size_t)T_DIM * B_DIM * H_DIM];

__device__ __forceinline__ void fma2(u64 &acc, u64 a, u64 b) {
    asm("fma.rn.f32x2 %0, %1, %2, %0;" : "+l"(acc) : "l"(a), "l"(b));
}
__device__ __forceinline__ float f2sum(u64 v) {
    float2 f = *reinterpret_cast<float2 *>(&v);
    return f.x + f.y;
}
__device__ __forceinline__ uint32_t smem_u32(const void *p) {
    uint32_t a;
    asm("{ .reg .u64 t; cvta.to.shared.u64 t, %1; cvt.u32.u64 %0, t; }" : "=r"(a) : "l"(p));
    return a;
}
__device__ __forceinline__ uint32_t mapa_u32(uint32_t addr, uint32_t rank) {
    uint32_t r;
    asm("mapa.shared::cluster.u32 %0, %1, %2;" : "=r"(r) : "r"(addr), "r"(rank));
    return r;
}
__device__ __forceinline__ void mbar_init(uint32_t a, uint32_t cnt) {
    asm volatile("mbarrier.init.shared.b64 [%0], %1;" :: "r"(a), "r"(cnt) : "memory");
}
__device__ __forceinline__ void mbar_expect_tx(uint32_t a, uint32_t tx) {
    asm volatile("mbarrier.arrive.expect_tx.shared.b64 _, [%0], %1;" :: "r"(a), "r"(tx) : "memory");
}
// BOUNDED wait: identical fast path; on protocol failure gives up after ~32K
// polls instead of hanging the GPU.
__device__ __forceinline__ void mbar_wait(uint32_t a, uint32_t parity) {
    for (int i = 0; i < (1 << 15); i++) {
        uint32_t done;
        asm volatile(
            "{\n\t.reg .pred p;\n\t"
            "mbarrier.try_wait.parity.acquire.cta.shared::cta.b64 p, [%1], %2;\n\t"
            "selp.b32 %0, 1, 0, p;\n\t}"
            : "=r"(done) : "r"(a), "r"(parity) : "memory");
        if (done) return;
    }
}
__device__ __forceinline__ void dsmem_bulk(uint32_t dst_cluster, uint32_t src_cta,
                                           uint32_t bytes, uint32_t mbar_cluster) {
    asm volatile(
        "cp.async.bulk.shared::cluster.shared::cta.mbarrier::complete_tx::bytes "
        "[%0], [%1], %2, [%3];"
        :: "r"(dst_cluster), "r"(src_cta), "r"(bytes), "r"(mbar_cluster) : "memory");
}
#define FENCE_ASYNC() asm volatile("fence.proxy.async.shared::cta;" ::: "memory")

// mma.sync m16n8k16 bf16 (sm_80+ baseline -> compiles for plain sm_100).
__device__ __forceinline__ void hmma(float *c, const uint32_t *a, uint32_t b0, uint32_t b1) {
    asm volatile(
        "mma.sync.aligned.m16n8k16.row.col.f32.bf16.bf16.f32 "
        "{%0,%1,%2,%3}, {%4,%5,%6,%7}, {%8,%9}, {%0,%1,%2,%3};"
        : "+f"(c[0]), "+f"(c[1]), "+f"(c[2]), "+f"(c[3])
        : "r"(a[0]), "r"(a[1]), "r"(a[2]), "r"(a[3]), "r"(b0), "r"(b1));
}
__device__ __forceinline__ void ldsm2t(uint32_t &b0, uint32_t &b1, uint32_t addr) {
    asm volatile("ldmatrix.sync.aligned.m8n8.x2.trans.shared.b16 {%0,%1}, [%2];"
                 : "=r"(b0), "=r"(b1) : "r"(addr));
}
__device__ __forceinline__ void split_pack(float2 v, uint32_t &hi, uint32_t &lo) {
    const __nv_bfloat16 h0 = __float2bfloat16_rn(v.x);
    const __nv_bfloat16 h1 = __float2bfloat16_rn(v.y);
    const __nv_bfloat16 l0 = __float2bfloat16_rn(v.x - __bfloat162float(h0));
    const __nv_bfloat16 l1 = __float2bfloat16_rn(v.y - __bfloat162float(h1));
    hi = (uint32_t)*reinterpret_cast<const uint16_t *>(&h0)
       | ((uint32_t)*reinterpret_cast<const uint16_t *>(&h1) << 16);
    lo = (uint32_t)*reinterpret_cast<const uint16_t *>(&l0)
       | ((uint32_t)*reinterpret_cast<const uint16_t *>(&l1) << 16);
}
__device__ __forceinline__ float tanh_fast(float s) {
    float e = __expf(2.0f * s);
    return 1.0f - __fdividef(2.0f, e + 1.0f);
}

// ---------------------------------------------------------------------------
// Kernel 1: xin GEMM, unchanged (known good).
// ---------------------------------------------------------------------------
__global__ void __launch_bounds__(256, 1)
xin_gemm(const float *__restrict__ x, const float *__restrict__ W_in,
         const float *__restrict__ b_in, const float *__restrict__ b_lat) {
    __shared__ float As[2][128 * 16];
    __shared__ float Bs[2][128 * 18];

    const int tid = threadIdx.x;
    const int tx = tid & 15;
    const int ty = tid >> 4;
    const int m0 = blockIdx.y * 128;
    const int n0 = blockIdx.x * 128;

    const int a_row0 = tid >> 2, a_c4 = tid & 3;
    const int b_row0 = tid >> 3, b_cp = tid & 7;

    float4 ra[2];
    float2 rb[4];

#pragma unroll
    for (int u = 0; u < 2; u++)
        ra[u] = *reinterpret_cast<const float4 *>(
            &x[(size_t)(m0 + a_row0 + u * 64) * D_DIM + a_c4 * 4]);
#pragma unroll
    for (int u = 0; u < 4; u++)
        rb[u] = *reinterpret_cast<const float2 *>(
            &W_in[(size_t)(n0 + b_row0 + u * 32) * D_DIM + b_cp * 2]);
#pragma unroll
    for (int u = 0; u < 2; u++)
        *reinterpret_cast<float4 *>(&As[0][(a_row0 + u * 64) * 16 + a_c4 * 4]) = ra[u];
#pragma unroll
    for (int u = 0; u < 4; u++)
        *reinterpret_cast<float2 *>(&Bs[0][(b_row0 + u * 32) * 18 + b_cp * 2]) = rb[u];
    __syncthreads();

    u64 acc[8][8];
#pragma unroll
    for (int i = 0; i < 8; i++)
#pragma unroll
        for (int j = 0; j < 8; j++) acc[i][j] = 0ull;

#pragma unroll 1
    for (int it = 0; it < 16; it++) {
        const int cur = it & 1;
        if (it < 15) {
            const int kc = (it + 1) * 16;
#pragma unroll
            for (int u = 0; u < 2; u++)
                ra[u] = *reinterpret_cast<const float4 *>(
                    &x[(size_t)(m0 + a_row0 + u * 64) * D_DIM + kc + a_c4 * 4]);
#pragma unroll
            for (int u = 0; u < 4; u++)
                rb[u] = *reinterpret_cast<const float2 *>(
                    &W_in[(size_t)(n0 + b_row0 + u * 32) * D_DIM + kc + b_cp * 2]);
        }

        const u64 *As2 = reinterpret_cast<const u64 *>(As[cur]);
        const u64 *Bs2 = reinterpret_cast<const u64 *>(Bs[cur]);
#pragma unroll
        for (int kp = 0; kp < 8; kp++) {
            u64 a2[8], b2[8];
#pragma unroll
            for (int i = 0; i < 8; i++) a2[i] = As2[(ty * 8 + i) * 8 + kp];
#pragma unroll
            for (int j = 0; j < 8; j++) b2[j] = Bs2[(tx + 16 * j) * 9 + kp];
#pragma unroll
            for (int i = 0; i < 8; i++)
#pragma unroll
                for (int j = 0; j < 8; j++) fma2(acc[i][j], a2[i], b2[j]);
        }

        if (it < 15) {
            const int nxt = cur ^ 1;
#pragma unroll
            for (int u = 0; u < 2; u++)
                *reinterpret_cast<float4 *>(&As[nxt][(a_row0 + u * 64) * 16 + a_c4 * 4]) = ra[u];
#pragma unroll
            for (int u = 0; u < 4; u++)
                *reinterpret_cast<float2 *>(&Bs[nxt][(b_row0 + u * 32) * 18 + b_cp * 2]) = rb[u];
            __syncthreads();
        }
    }

#pragma unroll
    for (int j = 0; j < 8; j++) {
        int n = n0 + tx + 16 * j;
        float bias = __ldg(&b_in[n]) + __ldg(&b_lat[n]);
#pragma unroll
        for (int i = 0; i < 8; i++) {
            g_xin[(size_t)(m0 + ty * 8 + i) * H_DIM + n] = f2sum(acc[i][j]) + bias;
        }
    }
}

// ---------------------------------------------------------------------------
// Kernel 2: HMMA (mma.sync bf16-split) scan. 16 clusters x 8 CTAs, 256 thr.
// Warp w: M-tile mt=w>>1 (16 j rows), k-half kh=w&1 (256 k). W A-fragments
// (hi+lo bf16 split) are REGISTER-RESIDENT for the whole scan.
// h smem layout [k][b]: 512 rows x 8 bf16 (16B) per split-half, organized as
// 8 rank blocks of {hi 1KB, lo 1KB} so producer slices bulk-copy directly.
// B-fragments come via ldmatrix.x2.trans (conflict-free at 16B row stride).
// 4 MMA chains/ktile into 4 independent accumulators; k-pair warps reduce
// through a padded Dsm; epilogue adds xin (prefetched 1 step ahead) + tanh.
// DSMEM ring transport as R6 (single expect group, race-free posting order).
//
// smem bytes:
//   [0,16)           mbars: buf0@0, buf1@8
//   [64,32832)       hbuf: 2 bufs x 8 ranks x {hi 1KB, lo 1KB}
//   [32832,35136)    Dsm: 8 (b) x 72 floats
// ---------------------------------------------------------------------------
#define MB_OFF     0
#define HBUF_OFF   64
#define BUF_STRIDE 16384
#define DSM_OFF    32832
#define SMEM_SCAN_BYTES 35200

__global__ void __cluster_dims__(8, 1, 1) __launch_bounds__(256, 1)
rnn_scan(const float *__restrict__ h0, const float *__restrict__ W_lat,
         float *__restrict__ out) {
    extern __shared__ char smem[];
    const uint32_t sbase = smem_u32(smem);
    float *Dsm = reinterpret_cast<float *>(smem + DSM_OFF);

    const int tid = threadIdx.x;
    const int lane = tid & 31;
    const int w = tid >> 5;
    const int mt = w >> 1;        // M-tile (16 j rows)
    const int kh = w & 1;         // k-half (256 k)
    const int r = blockIdx.x & 7;
    const int g = blockIdx.x >> 3;
    const int j0g = r * 64;
    const int b0 = g * 8;

    if (tid < 2) mbar_init(sbase + MB_OFF + tid * 8, 1);

    // ---- W A-fragments into registers (hi/lo split), one-time ----
    const int fg = lane >> 2;          // fragment row group 0..7
    const int fc = (lane & 3) * 2;     // fragment col pair base
    uint32_t whi[16][4], wlo[16][4];
    {
        const int r0 = j0g + mt * 16 + fg;
        const int r1 = r0 + 8;
#pragma unroll
        for (int q = 0; q < 16; q++) {
            const int kb = kh * 256 + q * 16 + fc;
            float2 v;
            v = *reinterpret_cast<const float2 *>(&W_lat[(size_t)r0 * H_DIM + kb]);
            split_pack(v, whi[q][0], wlo[q][0]);
            v = *reinterpret_cast<const float2 *>(&W_lat[(size_t)r1 * H_DIM + kb]);
            split_pack(v, whi[q][1], wlo[q][1]);
            v = *reinterpret_cast<const float2 *>(&W_lat[(size_t)r0 * H_DIM + kb + 8]);
            split_pack(v, whi[q][2], wlo[q][2]);
            v = *reinterpret_cast<const float2 *>(&W_lat[(size_t)r1 * H_DIM + kb + 8]);
            split_pack(v, whi[q][3], wlo[q][3]);
        }
    }

    // ---- preload h(-1) = h0 into buf 1 ----
    for (int i = tid; i < 8 * 512; i += 256) {
        const int b = i & 7, k = i >> 3;
        const float hv = h0[(size_t)(b0 + b) * H_DIM + k];
        const __nv_bfloat16 hi = __float2bfloat16_rn(hv);
        const __nv_bfloat16 lo = __float2bfloat16_rn(hv - __bfloat162float(hi));
        char *base = smem + HBUF_OFF + BUF_STRIDE + (k >> 6) * 2048 + (k & 63) * 16 + b * 2;
        *reinterpret_cast<__nv_bfloat16 *>(base) = hi;
        *reinterpret_cast<__nv_bfloat16 *>(base + 1024) = lo;
    }
    __syncthreads();
    // Expect for h(0) BEFORE any peer can send it (cluster barrier follows).
    if (tid == 0) mbar_expect_tx(sbase + MB_OFF + 0, 7 * 2048u);
    asm volatile("barrier.cluster.arrive.aligned;" ::: "memory");
    asm volatile("barrier.cluster.wait.aligned;" ::: "memory");

    // Epilogue mapping: b = warp id, j = lane*2 (+1).
    const int bE = w;
    const int jE = lane * 2;
    float *const out_base = out + (size_t)(b0 + bE) * H_DIM + j0g + jE;
    const float *const xin_b = g_xin + (size_t)(b0 + bE) * H_DIM + j0g + jE;

    const uint32_t lrow16 = (uint32_t)(lane & 15) * 16;
    int par[2] = {0, 0};

    float2 xpre = __ldcg(reinterpret_cast<const float2 *>(xin_b));

    for (int t = 0; t < T_DIM; t++) {
        float2 xnext = make_float2(0.f, 0.f);
        if (t + 1 < T_DIM)
            xnext = __ldcg(reinterpret_cast<const float2 *>(
                xin_b + (size_t)(t + 1) * B_DIM * H_DIM));

        const int rb = (t - 1) & 1;   // buffer with h(t-1); t=0 -> preloaded buf1
        if (t > 0) { mbar_wait(sbase + MB_OFF + rb * 8, par[rb]); par[rb] ^= 1; }

        // ---- GEMM: 16 ktiles x 4 chains into 4 independent accumulators ----
        float acc[4][4];
#pragma unroll
        for (int i = 0; i < 4; i++)
#pragma unroll
            for (int j = 0; j < 4; j++) acc[i][j] = 0.f;

        const uint32_t hb = sbase + HBUF_OFF + (uint32_t)rb * BUF_STRIDE;
#pragma unroll
        for (int q = 0; q < 16; q++) {
            const int k0 = kh * 256 + q * 16;
            const uint32_t addr = hb + (uint32_t)(k0 >> 6) * 2048
                                + (uint32_t)(k0 & 63) * 16 + lrow16;
            uint32_t bh0, bh1, bl0, bl1;
            ldsm2t(bh0, bh1, addr);
            ldsm2t(bl0, bl1, addr + 1024);
            hmma(acc[0], whi[q], bh0, bh1);
            hmma(acc[1], wlo[q], bh0, bh1);
            hmma(acc[2], whi[q], bl0, bl1);
            hmma(acc[3], wlo[q], bl0, bl1);
        }
        float c4[4];
#pragma unroll
        for (int i = 0; i < 4; i++)
            c4[i] = (acc[0][i] + acc[1][i]) + (acc[2][i] + acc[3][i]);

        // ---- cross-warp k-pair reduce through Dsm[b][72] ----
        // C frag: c0=(fg, fc), c1=(fg, fc+1), c2=(fg+8, fc), c3=(fg+8, fc+1)
        {
            float *d0 = Dsm + fc * 72 + mt * 16 + fg;
            if (kh == 0) {
                d0[0] = c4[0]; d0[72] = c4[1]; d0[8] = c4[2]; d0[80] = c4[3];
            }
            __syncthreads();
            if (kh == 1) {
                d0[0] += c4[0]; d0[72] += c4[1]; d0[8] += c4[2]; d0[80] += c4[3];
            }
            __syncthreads();
        }

        // ---- epilogue: 2 outputs per thread ----
        const float2 dv = *reinterpret_cast<const float2 *>(&Dsm[bE * 72 + jE]);
        const float res0 = tanh_fast(dv.x + xpre.x);
        const float res1 = tanh_fast(dv.y + xpre.y);
        __stcg(reinterpret_cast<float2 *>(out_base + (size_t)t * B_DIM * H_DIM),
               make_float2(res0, res1));
        xpre = xnext;

        // Expect for h(t+1) BEFORE sending h(t) (closes the tx/expect race:
        // a peer can send h(t+1) only after it receives our h(t)).
        if (tid == 0 && t + 1 < T_DIM)
            mbar_expect_tx(sbase + MB_OFF + ((t + 1) & 1) * 8, 7 * 2048u);

        if (t < T_DIM - 1) {
            // Stage own slice into buf(t&1) rank-r block, [k][b] layout.
            uint32_t hi0, lo0;
            split_pack(make_float2(res0, res1), hi0, lo0);
            char *bb = smem + HBUF_OFF + (t & 1) * BUF_STRIDE + r * 2048;
            *reinterpret_cast<__nv_bfloat16 *>(bb + jE * 16 + bE * 2) =
                *reinterpret_cast<__nv_bfloat16 *>(&hi0);
            *reinterpret_cast<__nv_bfloat16 *>(bb + (jE + 1) * 16 + bE * 2) =
                *(reinterpret_cast<__nv_bfloat16 *>(&hi0) + 1);
            *reinterpret_cast<__nv_bfloat16 *>(bb + 1024 + jE * 16 + bE * 2) =
                *reinterpret_cast<__nv_bfloat16 *>(&lo0);
            *reinterpret_cast<__nv_bfloat16 *>(bb + 1024 + (jE + 1) * 16 + bE * 2) =
                *(reinterpret_cast<__nv_bfloat16 *>(&lo0) + 1);
            FENCE_ASYNC();
            __syncthreads();
            if (tid < 7) {
                const uint32_t peer = (uint32_t)((r + 1 + tid) & 7);
                const uint32_t src = sbase + HBUF_OFF + (t & 1) * BUF_STRIDE + r * 2048;
                const uint32_t mb = sbase + MB_OFF + (t & 1) * 8;
                dsmem_bulk(mapa_u32(src, peer), src, 2048u, mapa_u32(mb, peer));
            }
        }
    }

    asm volatile("barrier.cluster.arrive.aligned;" ::: "memory");
    asm volatile("barrier.cluster.wait.aligned;" ::: "memory");
}

// ---------------------------------------------------------------------------
extern "C" void kernel_launch(void *const *d_in, const int *in_sizes, int n_in,
                              void *d_out, int out_size) {
    const float *x     = (const float *)d_in[0];
    const float *h     = (const float *)d_in[1];
    const float *W_in  = (const float *)d_in[2];
    const float *b_in  = (const float *)d_in[3];
    const float *W_lat = (const float *)d_in[4];
    const float *b_lat = (const float *)d_in[5];
    float *out = (float *)d_out;

    dim3 gx(H_DIM / 128, (T_DIM * B_DIM) / 128);   // (4, 512)
    xin_gemm<<<gx, 256>>>(x, W_in, b_in, b_lat);

    cudaFuncSetAttribute(rnn_scan, cudaFuncAttributeMaxDynamicSharedMemorySize,
                         SMEM_SCAN_BYTES);
    rnn_scan<<<B_DIM, 256, SMEM_SCAN_BYTES>>>(h, W_lat, out);
}